// round 5
// baseline (speedup 1.0000x reference)
#include <cuda_runtime.h>
#include <cuda_bf16.h>

// Shapes (fixed by the reference)
#define B_   32
#define C_   512
#define N_   1024       // H*W
#define M_   77
#define MP_  128        // padded M
#define TD_  768
#define NH_  8
#define HD_  64
#define SCALE_ 0.125f   // 1/sqrt(64)

// Scratch (static __device__ — allocation-free per harness rules)
__device__ float g_Qt[B_ * C_ * N_];     // 64 MB  Qt[b][c][n]
__device__ float g_Kt[B_ * C_ * MP_];    //  8 MB  Kt[b][c][m]
__device__ float g_Vt[B_ * C_ * MP_];    //  8 MB
__device__ float g_textT[B_ * TD_ * MP_];// 12 MB  textT[b][t][m] (zero padded m>=77)

typedef unsigned long long ull;
union F2U { float2 f; ull u; };
union F4U { float4 v; ull u[2]; float f[4]; };

// Packed fp32x2 FMA (Blackwell FFMA2 — only reachable via PTX)
__device__ __forceinline__ ull ffma2(ull a, ull b, ull c) {
    ull d;
    asm("fma.rn.f32x2 %0, %1, %2, %3;" : "=l"(d) : "l"(a), "l"(b), "l"(c));
    return d;
}
__device__ __forceinline__ ull pack2(float x, float y) {
    ull r; asm("mov.b64 %0, {%1, %2};" : "=l"(r) : "f"(x), "f"(y)); return r;
}
__device__ __forceinline__ float2 unpack2(ull v) {
    float2 r; asm("mov.b64 {%0, %1}, %2;" : "=f"(r.x), "=f"(r.y) : "l"(v)); return r;
}

// ---------------------------------------------------------------------------
// 1) text_emb [B][77][768] -> textT [B][768][128], zero-padded in m
// ---------------------------------------------------------------------------
__global__ void transpose_text_kernel(const float* __restrict__ text) {
    __shared__ float tile[32][33];
    const int b  = blockIdx.z;
    const int t0 = blockIdx.x << 5;   // over 768 (24 blocks)
    const int m0 = blockIdx.y << 5;   // over 128 (4 blocks)
    const int tx = threadIdx.x, ty = threadIdx.y;
#pragma unroll
    for (int i = ty; i < 32; i += 8) {
        const int m = m0 + i;
        float v = 0.0f;
        if (m < M_) v = text[(b * M_ + m) * TD_ + t0 + tx];
        tile[i][tx] = v;
    }
    __syncthreads();
#pragma unroll
    for (int i = ty; i < 32; i += 8) {
        g_textT[(b * TD_ + t0 + i) * MP_ + m0 + tx] = tile[tx][i];
    }
}

// ---------------------------------------------------------------------------
// 2) SGEMM 128x128xK, BK=16, double-buffered smem, ONE barrier per k-tile.
//    256 threads, 8x8 microtile, FFMA2 inner product.
//    C[row][col] = sum_k A[row][k] * B[k][col] + bias[row]
//    All dims are multiples of the tile sizes -> no guards.
// ---------------------------------------------------------------------------
__device__ __forceinline__ void sgemm_body(
    const float* __restrict__ A, const float* __restrict__ B,
    float* __restrict__ C, const float* __restrict__ bias,
    int K, int ldb, int ldc)
{
    __shared__ float As[2][16][128];   // [stage][k][m]
    __shared__ float Bs[2][16][128];   // [stage][k][n]

    const int tid     = threadIdx.x;
    const int rowBase = blockIdx.y << 7;
    const int colBase = blockIdx.x << 7;

    const int a_m = tid >> 1;            // 0..127
    const int a_k = (tid & 1) << 3;      // 0 or 8
    const int b_k = tid >> 5;            // 0..7 (+8 for second row)
    const int b_n = (tid & 31) << 2;     // 0..124 step 4
    const int m0  = (tid >> 4) << 3, n0 = (tid & 15) << 3;

    const float* Aptr  = A + (rowBase + a_m) * K + a_k;
    const float* Bptr  = B + b_k * ldb + colBase + b_n;
    const float* Bptr2 = Bptr + 8 * ldb;

    ull acc[8][4];
#pragma unroll
    for (int i = 0; i < 8; i++)
#pragma unroll
        for (int j = 0; j < 4; j++) acc[i][j] = 0ull;

    // prefetch + store stage 0
    float4 aR0 = *reinterpret_cast<const float4*>(Aptr);
    float4 aR1 = *reinterpret_cast<const float4*>(Aptr + 4);
    float4 bR0 = *reinterpret_cast<const float4*>(Bptr);
    float4 bR1 = *reinterpret_cast<const float4*>(Bptr2);
    As[0][a_k + 0][a_m] = aR0.x;  As[0][a_k + 1][a_m] = aR0.y;
    As[0][a_k + 2][a_m] = aR0.z;  As[0][a_k + 3][a_m] = aR0.w;
    As[0][a_k + 4][a_m] = aR1.x;  As[0][a_k + 5][a_m] = aR1.y;
    As[0][a_k + 6][a_m] = aR1.z;  As[0][a_k + 7][a_m] = aR1.w;
    *reinterpret_cast<float4*>(&Bs[0][b_k][b_n])     = bR0;
    *reinterpret_cast<float4*>(&Bs[0][b_k + 8][b_n]) = bR1;
    __syncthreads();

    const int nT = K >> 4;
    for (int t = 0; t < nT; t++) {
        const int cur = t & 1;
        const int nxt = cur ^ 1;
        if (t + 1 < nT) {   // global prefetch of next tile (latency hidden under compute)
            const float* An = Aptr + (t + 1) * 16;
            const float* Bn = Bptr + (t + 1) * 16 * ldb;
            aR0 = *reinterpret_cast<const float4*>(An);
            aR1 = *reinterpret_cast<const float4*>(An + 4);
            bR0 = *reinterpret_cast<const float4*>(Bn);
            bR1 = *reinterpret_cast<const float4*>(Bn + 8 * ldb);
        }
#pragma unroll
        for (int kk = 0; kk < 16; kk++) {
            F4U a0; a0.v = *reinterpret_cast<const float4*>(&As[cur][kk][m0]);
            F4U a1; a1.v = *reinterpret_cast<const float4*>(&As[cur][kk][m0 + 4]);
            F4U b0; b0.v = *reinterpret_cast<const float4*>(&Bs[cur][kk][n0]);
            F4U b1; b1.v = *reinterpret_cast<const float4*>(&Bs[cur][kk][n0 + 4]);
            ull bb[4] = { b0.u[0], b0.u[1], b1.u[0], b1.u[1] };
            ull ad[8];
#pragma unroll
            for (int i = 0; i < 4; i++) {
                ad[i]     = pack2(a0.f[i], a0.f[i]);
                ad[4 + i] = pack2(a1.f[i], a1.f[i]);
            }
#pragma unroll
            for (int i = 0; i < 8; i++)
#pragma unroll
                for (int j = 0; j < 4; j++)
                    acc[i][j] = ffma2(ad[i], bb[j], acc[i][j]);
        }
        if (t + 1 < nT) {   // store prefetched tile into the other stage
            As[nxt][a_k + 0][a_m] = aR0.x;  As[nxt][a_k + 1][a_m] = aR0.y;
            As[nxt][a_k + 2][a_m] = aR0.z;  As[nxt][a_k + 3][a_m] = aR0.w;
            As[nxt][a_k + 4][a_m] = aR1.x;  As[nxt][a_k + 5][a_m] = aR1.y;
            As[nxt][a_k + 6][a_m] = aR1.z;  As[nxt][a_k + 7][a_m] = aR1.w;
            *reinterpret_cast<float4*>(&Bs[nxt][b_k][b_n])     = bR0;
            *reinterpret_cast<float4*>(&Bs[nxt][b_k + 8][b_n]) = bR1;
            __syncthreads();
        }
    }

#pragma unroll
    for (int i = 0; i < 8; i++) {
        const int r = rowBase + m0 + i;
        const float bi = bias[r];
        float* crow = C + r * ldc + colBase + n0;
        F2U p0, p1, p2, p3;
        p0.u = acc[i][0]; p1.u = acc[i][1]; p2.u = acc[i][2]; p3.u = acc[i][3];
        float4 o0 = make_float4(p0.f.x + bi, p0.f.y + bi, p1.f.x + bi, p1.f.y + bi);
        float4 o1 = make_float4(p2.f.x + bi, p2.f.y + bi, p3.f.x + bi, p3.f.y + bi);
        *reinterpret_cast<float4*>(crow)     = o0;
        *reinterpret_cast<float4*>(crow + 4) = o1;
    }
}

// Qt[b] = Wq(512x512) @ x[b](512x1024) + bq     grid (8,4,32)
__global__ __launch_bounds__(256, 2)
void sgemm_q_kernel(const float* __restrict__ Wq, const float* __restrict__ x,
                    const float* __restrict__ bq) {
    const int b = blockIdx.z;
    sgemm_body(Wq, x + b * C_ * N_, g_Qt + b * C_ * N_, bq, C_, N_, N_);
}

// Kt/Vt[b] = W(512x768) @ textT[b](768x128) + bias   grid (1,4,64), z = 2*b+sel
__global__ __launch_bounds__(256, 2)
void sgemm_kv_kernel(const float* __restrict__ Wk, const float* __restrict__ Wv,
                     const float* __restrict__ bk, const float* __restrict__ bv) {
    const int z = blockIdx.z;
    const int b = z >> 1;
    const bool isV = (z & 1) != 0;
    const float* A    = isV ? Wv : Wk;
    const float* bias = isV ? bv : bk;
    float* Cout = (isV ? g_Vt : g_Kt) + b * C_ * MP_;
    sgemm_body(A, g_textT + b * TD_ * MP_, Cout, bias, TD_, MP_, MP_);
}

// ---------------------------------------------------------------------------
// 3) Fused attention v2: block = (128 queries, head, batch), 256 threads,
//    TWO threads per query (d split 32+32, one shfl per score).
//    Scores live in SHARED memory (no register spills), m-loops unroll 7.
//    K/V head tiles in smem; output written directly in [B][C][H][W] layout.
// ---------------------------------------------------------------------------
#define ATTN_SMEM_FLOATS (2 * M_ * 68 + M_ * 128 + 80)
#define ATTN_SMEM_BYTES  (ATTN_SMEM_FLOATS * 4)

__global__ __launch_bounds__(256)
void attn_kernel(const int* __restrict__ mask, float* __restrict__ out) {
    extern __shared__ float sm[];
    float* Ksm = sm;                        // [77][68]
    float* Vsm = sm + M_ * 68;              // [77][68]
    float* Ssm = sm + 2 * M_ * 68;          // [77][128]
    float* msk = sm + 2 * M_ * 68 + M_ * 128;

    const int tid = threadIdx.x;
    const int b = blockIdx.z, hd = blockIdx.y;
    const int h = tid & 1;                  // which 32-wide d-half
    const int q = tid >> 1;                 // 0..127 query within block
    const int n = (blockIdx.x << 7) + q;
    const int dBase = h << 5;

    const int kvBase = (b * C_ + hd * HD_) * MP_;
    const int qBase  = (b * C_ + hd * HD_) * N_ + n;

    // Stage K/V head tile (coalesced over m) + mask
    for (int i = tid; i < HD_ * 128; i += 256) {
        const int d = i >> 7, m = i & 127;
        if (m < M_) {
            Ksm[m * 68 + d] = g_Kt[kvBase + d * MP_ + m];
            Vsm[m * 68 + d] = g_Vt[kvBase + d * MP_ + m];
        }
    }
    if (tid < M_) msk[tid] = (mask[b * M_ + tid] != 0) ? 0.0f : -1e30f;

    // Per-thread half-query: 16 packed pairs
    ull q2[16];
#pragma unroll
    for (int j = 0; j < 16; j++) {
        float qx = g_Qt[qBase + (dBase + 2 * j) * N_];
        float qy = g_Qt[qBase + (dBase + 2 * j + 1) * N_];
        q2[j] = pack2(qx, qy);
    }
    __syncthreads();

    // QK: partial dot over this half's 32 dims, pair-reduce via shfl, -> Ssm
#pragma unroll 7
    for (int m = 0; m < M_; m++) {
        const float* kr = &Ksm[m * 68 + dBase];
        ull c0 = 0ull, c1 = 0ull, c2 = 0ull, c3 = 0ull;
#pragma unroll
        for (int j = 0; j < 4; j++) {
            F4U k0; k0.v = *reinterpret_cast<const float4*>(kr + 8 * j);
            F4U k1; k1.v = *reinterpret_cast<const float4*>(kr + 8 * j + 4);
            c0 = ffma2(q2[4 * j + 0], k0.u[0], c0);
            c1 = ffma2(q2[4 * j + 1], k0.u[1], c1);
            c2 = ffma2(q2[4 * j + 2], k1.u[0], c2);
            c3 = ffma2(q2[4 * j + 3], k1.u[1], c3);
        }
        float2 r0 = unpack2(c0), r1 = unpack2(c1), r2 = unpack2(c2), r3 = unpack2(c3);
        float part = ((r0.x + r0.y) + (r1.x + r1.y)) + ((r2.x + r2.y) + (r3.x + r3.y));
        float other = __shfl_xor_sync(0xFFFFFFFFu, part, 1);
        float s = (part + other) * SCALE_ + msk[m];
        if (h == 0) Ssm[m * 128 + q] = s;
    }
    __syncwarp();   // h==1 threads read partner's stores

    // Softmax stats over the column q
    float mx = -1e30f;
#pragma unroll 7
    for (int m = 0; m < M_; m++) mx = fmaxf(mx, Ssm[m * 128 + q]);
    float sum = 0.0f;
#pragma unroll 7
    for (int m = 0; m < M_; m++) {
        const float p = __expf(Ssm[m * 128 + q] - mx);
        Ssm[m * 128 + q] = p;   // both pair-threads write identical value
        sum += p;
    }
    const float inv = 1.0f / sum;

    // PV for this half's 32 dims
    ull o2[16];
#pragma unroll
    for (int j = 0; j < 16; j++) o2[j] = 0ull;
#pragma unroll 7
    for (int m = 0; m < M_; m++) {
        const float p = Ssm[m * 128 + q];
        const ull pm = pack2(p, p);
        const float* vr = &Vsm[m * 68 + dBase];
#pragma unroll
        for (int j = 0; j < 4; j++) {
            F4U v0; v0.v = *reinterpret_cast<const float4*>(vr + 8 * j);
            F4U v1; v1.v = *reinterpret_cast<const float4*>(vr + 8 * j + 4);
            o2[4 * j + 0] = ffma2(pm, v0.u[0], o2[4 * j + 0]);
            o2[4 * j + 1] = ffma2(pm, v0.u[1], o2[4 * j + 1]);
            o2[4 * j + 2] = ffma2(pm, v1.u[0], o2[4 * j + 2]);
            o2[4 * j + 3] = ffma2(pm, v1.u[1], o2[4 * j + 3]);
        }
    }
#pragma unroll
    for (int j = 0; j < 16; j++) {
        float2 o = unpack2(o2[j]);
        out[qBase + (dBase + 2 * j) * N_]     = o.x * inv;
        out[qBase + (dBase + 2 * j + 1) * N_] = o.y * inv;
    }
}

// ---------------------------------------------------------------------------
// kernel_launch — inputs per metadata order:
// 0:x 1:text_emb 2:attention_mask 3:Wq 4:bq 5:Wk 6:bk 7:Wv 8:bv
// ---------------------------------------------------------------------------
extern "C" void kernel_launch(void* const* d_in, const int* in_sizes, int n_in,
                              void* d_out, int out_size) {
    (void)in_sizes; (void)n_in; (void)out_size;
    const float* x    = (const float*)d_in[0];
    const float* text = (const float*)d_in[1];
    const int*   mask = (const int*)d_in[2];
    const float* Wq   = (const float*)d_in[3];
    const float* bq   = (const float*)d_in[4];
    const float* Wk   = (const float*)d_in[5];
    const float* bk   = (const float*)d_in[6];
    const float* Wv   = (const float*)d_in[7];
    const float* bv   = (const float*)d_in[8];
    float* out = (float*)d_out;

    cudaFuncSetAttribute(attn_kernel, cudaFuncAttributeMaxDynamicSharedMemorySize,
                         ATTN_SMEM_BYTES);

    transpose_text_kernel<<<dim3(24, 4, 32), dim3(32, 8)>>>(text);
    sgemm_kv_kernel<<<dim3(1, 4, 64), 256>>>(Wk, Wv, bk, bv);
    sgemm_q_kernel<<<dim3(8, 4, 32), 256>>>(Wq, x, bq);
    attn_kernel<<<dim3(8, 8, 32), 256, ATTN_SMEM_BYTES>>>(mask, out);
}

// round 8
// speedup vs baseline: 1.2510x; 1.2510x over previous
#include <cuda_runtime.h>
#include <cuda_bf16.h>
#include <mma.h>
#include <cstdint>

using namespace nvcuda;

// Shapes (fixed by the reference)
#define B_   32
#define C_   512
#define N_   1024       // H*W
#define M_   77
#define MP_  128        // padded M
#define TD_  768
#define NH_  8
#define HD_  64
#define SCALE_ 0.125f   // 1/sqrt(64)

// Scratch (static __device__ — allocation-free per harness rules)
__device__ float g_Qt[B_ * C_ * N_];     // 64 MB  Qt[b][c][n]
__device__ float g_Kt[B_ * C_ * MP_];    //  8 MB  Kt[b][c][m]
__device__ float g_Vt[B_ * C_ * MP_];    //  8 MB

typedef unsigned long long ull;
union F4U { float4 v; ull u[2]; float f[4]; };

// Packed fp32x2 FMA (for the SIMT attention kernel)
__device__ __forceinline__ ull ffma2(ull a, ull b, ull c) {
    ull d;
    asm("fma.rn.f32x2 %0, %1, %2, %3;" : "=l"(d) : "l"(a), "l"(b), "l"(c));
    return d;
}
__device__ __forceinline__ ull pack2(float x, float y) {
    ull r; asm("mov.b64 %0, {%1, %2};" : "=l"(r) : "f"(x), "f"(y)); return r;
}
__device__ __forceinline__ float2 unpack2(ull v) {
    float2 r; asm("mov.b64 {%0, %1}, %2;" : "=f"(r.x), "=f"(r.y) : "l"(v)); return r;
}
__device__ __forceinline__ uint32_t smem_u32(const void* p) {
    uint32_t a;
    asm("{ .reg .u64 t; cvta.to.shared.u64 t, %1; cvt.u32.u64 %0, t; }"
        : "=r"(a) : "l"(p));
    return a;
}
__device__ __forceinline__ void cp16(uint32_t dst, const float* src) {
    asm volatile("cp.async.cg.shared.global [%0], [%1], 16;"
                 :: "r"(dst), "l"(src));
}
// zero-fill variant: src-size 0 -> 16 bytes of zeros, src not dereferenced
__device__ __forceinline__ void cp16z(uint32_t dst, const float* src, bool valid) {
    const int sz = valid ? 16 : 0;
    asm volatile("cp.async.cg.shared.global [%0], [%1], 16, %2;"
                 :: "r"(dst), "l"(src), "r"(sz));
}

// ===========================================================================
// tf32 WMMA GEMM: C[m][n] = A[m][k] @ B + bias[m]
//   block 128x128, 8 warps (2m x 4n), warp tile 64x32 = 4x2 wmma 16x16x8 frags
//   k-tile 32, double-buffered cp.async staging.
//   BCOL=false: B source row-major [k][n] (x: k=channel, n=spatial)
//   BCOL=true : B source col-major rows [n][k] (text_emb rows; n>=M_ zero-filled)
// ===========================================================================
#define A_LD   36
#define BQ_LD  132
#define BC_LD  36
#define A_FLOATS   (128 * A_LD)          // 4608
#define B_FLOATS   (128 * BC_LD)         // 4608 (>= 32*BQ_LD = 4224)
#define BUF_FLOATS (A_FLOATS + B_FLOATS) // 9216
#define GEMM_SMEM  (2 * BUF_FLOATS * 4)  // 73728 bytes

template<bool BCOL>
__device__ __forceinline__ void gemm_body(
    const float* __restrict__ A, const float* __restrict__ Bsrc,
    float* __restrict__ Cout, const float* __restrict__ bias,
    int K, int lda, int ldb, int ldc)
{
    extern __shared__ float smem[];
    const uint32_t smem_addr = smem_u32(smem);
    const int tid = threadIdx.x;
    const int wid = tid >> 5, lane = tid & 31;
    const int wm = wid >> 2, wn = wid & 3;         // 2 x 4 warp grid
    const int rowBase = blockIdx.y << 7;
    const int colBase = blockIdx.x << 7;

    wmma::fragment<wmma::accumulator, 16, 16, 8, float> c[4][2];
#pragma unroll
    for (int i = 0; i < 4; i++)
#pragma unroll
        for (int j = 0; j < 2; j++) wmma::fill_fragment(c[i][j], 0.0f);

    auto stage = [&](int kt, int buf) {
        const uint32_t sA = smem_addr + buf * (BUF_FLOATS * 4);
        const uint32_t sB = sA + A_FLOATS * 4;
        const float* baseA = A + (size_t)rowBase * lda + kt * 32;
#pragma unroll
        for (int r4 = 0; r4 < 4; r4++) {            // A tile: [128][32]
            const int i4 = tid + (r4 << 8);
            const int row = i4 >> 3, c4 = (i4 & 7) << 2;
            cp16(sA + (uint32_t)(row * A_LD + c4) * 4, baseA + (size_t)row * lda + c4);
        }
        if (!BCOL) {                                 // B tile: [k=32][n=128]
            const float* baseB = Bsrc + (size_t)(kt * 32) * ldb + colBase;
#pragma unroll
            for (int r4 = 0; r4 < 4; r4++) {
                const int i4 = tid + (r4 << 8);
                const int k = i4 >> 5, n4 = (i4 & 31) << 2;
                cp16(sB + (uint32_t)(k * BQ_LD + n4) * 4, baseB + (size_t)k * ldb + n4);
            }
        } else {                                     // B tile: [n=128][k=32], pad n>=M_
            const float* baseB = Bsrc + kt * 32;
#pragma unroll
            for (int r4 = 0; r4 < 4; r4++) {
                const int i4 = tid + (r4 << 8);
                const int n = i4 >> 3, k4 = (i4 & 7) << 2;
                cp16z(sB + (uint32_t)(n * BC_LD + k4) * 4, baseB + (size_t)n * ldb + k4,
                      n < M_);
            }
        }
    };

    const int nkt = K >> 5;
    stage(0, 0);
    asm volatile("cp.async.commit_group;" ::: "memory");

    for (int kt = 0; kt < nkt; kt++) {
        const int buf = kt & 1;
        if (kt + 1 < nkt) {
            stage(kt + 1, buf ^ 1);
            asm volatile("cp.async.commit_group;" ::: "memory");
            asm volatile("cp.async.wait_group 1;" ::: "memory");
        } else {
            asm volatile("cp.async.wait_group 0;" ::: "memory");
        }
        __syncthreads();

        const float* As = smem + buf * BUF_FLOATS;
        const float* Bs = As + A_FLOATS;
#pragma unroll
        for (int ks = 0; ks < 4; ks++) {
            wmma::fragment<wmma::matrix_a, 16, 16, 8, wmma::precision::tf32,
                           wmma::row_major> a[4];
#pragma unroll
            for (int i = 0; i < 4; i++) {
                wmma::load_matrix_sync(a[i], As + (wm * 64 + i * 16) * A_LD + ks * 8, A_LD);
#pragma unroll
                for (int t = 0; t < a[i].num_elements; t++)
                    a[i].x[t] = wmma::__float_to_tf32(a[i].x[t]);
            }
#pragma unroll
            for (int j = 0; j < 2; j++) {
                if (!BCOL) {
                    wmma::fragment<wmma::matrix_b, 16, 16, 8, wmma::precision::tf32,
                                   wmma::row_major> b;
                    wmma::load_matrix_sync(b, Bs + ks * 8 * BQ_LD + (wn * 32 + j * 16),
                                           BQ_LD);
#pragma unroll
                    for (int t = 0; t < b.num_elements; t++)
                        b.x[t] = wmma::__float_to_tf32(b.x[t]);
#pragma unroll
                    for (int i = 0; i < 4; i++) wmma::mma_sync(c[i][j], a[i], b, c[i][j]);
                } else {
                    wmma::fragment<wmma::matrix_b, 16, 16, 8, wmma::precision::tf32,
                                   wmma::col_major> b;
                    wmma::load_matrix_sync(b, Bs + (wn * 32 + j * 16) * BC_LD + ks * 8,
                                           BC_LD);
#pragma unroll
                    for (int t = 0; t < b.num_elements; t++)
                        b.x[t] = wmma::__float_to_tf32(b.x[t]);
#pragma unroll
                    for (int i = 0; i < 4; i++) wmma::mma_sync(c[i][j], a[i], b, c[i][j]);
                }
            }
        }
        __syncthreads();   // staging buffers free for next prefetch / epilogue
    }

    // Epilogue: per-warp 16x16 smem patch, add bias, write row-major C
    float* patch = smem + wid * 256;
#pragma unroll
    for (int i = 0; i < 4; i++) {
        const int row0 = rowBase + wm * 64 + i * 16;
#pragma unroll
        for (int j = 0; j < 2; j++) {
            const int col0 = colBase + wn * 32 + j * 16;
            wmma::store_matrix_sync(patch, c[i][j], 16, wmma::mem_row_major);
            __syncwarp();
#pragma unroll
            for (int e = lane; e < 256; e += 32) {
                const int r = e >> 4, cc = e & 15;
                Cout[(size_t)(row0 + r) * ldc + col0 + cc] = patch[e] + bias[row0 + r];
            }
            __syncwarp();
        }
    }
}

// Qt[b] = Wq(512x512) @ x[b](512x1024) + bq   grid (8, 4, 32)
__global__ __launch_bounds__(256)
void gemm_q_kernel(const float* __restrict__ Wq, const float* __restrict__ x,
                   const float* __restrict__ bq) {
    const int b = blockIdx.z;
    gemm_body<false>(Wq, x + (size_t)b * C_ * N_, g_Qt + (size_t)b * C_ * N_,
                     bq, C_, C_, N_, N_);
}

// Kt/Vt[b] = W(512x768) @ text[b]^T + bias   grid (1, 4, 64), z = 2b+isV
__global__ __launch_bounds__(256)
void gemm_kv_kernel(const float* __restrict__ Wk, const float* __restrict__ Wv,
                    const float* __restrict__ text,
                    const float* __restrict__ bk, const float* __restrict__ bv) {
    const int z = blockIdx.z;
    const int b = z >> 1;
    const bool isV = (z & 1) != 0;
    gemm_body<true>(isV ? Wv : Wk, text + (size_t)b * M_ * TD_,
                    (isV ? g_Vt : g_Kt) + (size_t)b * C_ * MP_,
                    isV ? bv : bk, TD_, TD_, TD_, MP_);
}

// ---------------------------------------------------------------------------
// Fused attention (R4 variant — known-good; 128 thr, one query/thread)
// ---------------------------------------------------------------------------
__global__ __launch_bounds__(128)
void attn_kernel(const int* __restrict__ mask, float* __restrict__ out) {
    __shared__ float Ksm[M_][68];
    __shared__ float Vsm[M_][68];
    __shared__ float msk[M_];

    const int tid = threadIdx.x;
    const int b = blockIdx.z, h = blockIdx.y;
    const int n = (blockIdx.x << 7) + tid;

    const int kvBase = (b * C_ + h * HD_) * MP_;
    const int qBase  = (b * C_ + h * HD_) * N_ + n;

    ull q2[32];
#pragma unroll
    for (int j = 0; j < 32; j++) {
        float qx = g_Qt[qBase + (2 * j) * N_];
        float qy = g_Qt[qBase + (2 * j + 1) * N_];
        q2[j] = pack2(qx, qy);
    }

    if (tid < M_) {
#pragma unroll 4
        for (int d = 0; d < HD_; d++) {
            Ksm[tid][d] = g_Kt[kvBase + d * MP_ + tid];
            Vsm[tid][d] = g_Vt[kvBase + d * MP_ + tid];
        }
        msk[tid] = (mask[b * M_ + tid] != 0) ? 1.0f : 0.0f;
    }
    __syncthreads();

    float s[M_];
#pragma unroll
    for (int m = 0; m < M_; m++) {
        ull c0 = 0ull, c1 = 0ull, c2 = 0ull, c3 = 0ull;
#pragma unroll
        for (int j = 0; j < 8; j++) {
            F4U k0; k0.v = *reinterpret_cast<const float4*>(&Ksm[m][j * 8]);
            F4U k1; k1.v = *reinterpret_cast<const float4*>(&Ksm[m][j * 8 + 4]);
            c0 = ffma2(q2[4 * j + 0], k0.u[0], c0);
            c1 = ffma2(q2[4 * j + 1], k0.u[1], c1);
            c2 = ffma2(q2[4 * j + 2], k1.u[0], c2);
            c3 = ffma2(q2[4 * j + 3], k1.u[1], c3);
        }
        float2 r0 = unpack2(c0), r1 = unpack2(c1), r2 = unpack2(c2), r3 = unpack2(c3);
        s[m] = ((r0.x + r0.y) + (r1.x + r1.y)) + ((r2.x + r2.y) + (r3.x + r3.y));
    }

    float mx = -1e30f;
#pragma unroll
    for (int m = 0; m < M_; m++) {
        s[m] = (msk[m] != 0.0f) ? s[m] * SCALE_ : -1e30f;
        mx = fmaxf(mx, s[m]);
    }
    float sum = 0.0f;
#pragma unroll
    for (int m = 0; m < M_; m++) {
        float p = __expf(s[m] - mx);
        s[m] = p;
        sum += p;
    }
    const float inv = 1.0f / sum;

    ull o2[32];
#pragma unroll
    for (int j = 0; j < 32; j++) o2[j] = 0ull;
#pragma unroll
    for (int m = 0; m < M_; m++) {
        ull pm = pack2(s[m], s[m]);
#pragma unroll
        for (int j = 0; j < 16; j++) {
            F4U v4; v4.v = *reinterpret_cast<const float4*>(&Vsm[m][j * 4]);
            o2[2 * j]     = ffma2(pm, v4.u[0], o2[2 * j]);
            o2[2 * j + 1] = ffma2(pm, v4.u[1], o2[2 * j + 1]);
        }
    }
#pragma unroll
    for (int j = 0; j < 32; j++) {
        float2 o = unpack2(o2[j]);
        out[qBase + (2 * j) * N_]     = o.x * inv;
        out[qBase + (2 * j + 1) * N_] = o.y * inv;
    }
}

// ---------------------------------------------------------------------------
// kernel_launch — inputs: 0:x 1:text_emb 2:attention_mask 3:Wq 4:bq 5:Wk 6:bk 7:Wv 8:bv
// ---------------------------------------------------------------------------
extern "C" void kernel_launch(void* const* d_in, const int* in_sizes, int n_in,
                              void* d_out, int out_size) {
    (void)in_sizes; (void)n_in; (void)out_size;
    const float* x    = (const float*)d_in[0];
    const float* text = (const float*)d_in[1];
    const int*   mask = (const int*)d_in[2];
    const float* Wq   = (const float*)d_in[3];
    const float* bq   = (const float*)d_in[4];
    const float* Wk   = (const float*)d_in[5];
    const float* bk   = (const float*)d_in[6];
    const float* Wv   = (const float*)d_in[7];
    const float* bv   = (const float*)d_in[8];
    float* out = (float*)d_out;

    cudaFuncSetAttribute(gemm_q_kernel,  cudaFuncAttributeMaxDynamicSharedMemorySize,
                         GEMM_SMEM);
    cudaFuncSetAttribute(gemm_kv_kernel, cudaFuncAttributeMaxDynamicSharedMemorySize,
                         GEMM_SMEM);

    gemm_kv_kernel<<<dim3(1, 4, 64), 256, GEMM_SMEM>>>(Wk, Wv, text, bk, bv);
    gemm_q_kernel<<<dim3(8, 4, 32), 256, GEMM_SMEM>>>(Wq, x, bq);
    attn_kernel<<<dim3(8, 8, 32), 128>>>(mask, out);
}

// round 9
// speedup vs baseline: 1.6718x; 1.3364x over previous
#include <cuda_runtime.h>
#include <cuda_bf16.h>
#include <mma.h>
#include <cstdint>

using namespace nvcuda;

// Shapes (fixed by the reference)
#define B_   32
#define C_   512
#define N_   1024       // H*W
#define M_   77
#define MP_  128        // padded M
#define TD_  768
#define NH_  8
#define HD_  64
#define SCALE_ 0.125f   // 1/sqrt(64)

// Scratch (static __device__ — allocation-free per harness rules)
__device__ float g_Qt[B_ * C_ * N_];     // 64 MB  Qt[b][c][n]
__device__ float g_Kt[B_ * C_ * MP_];    //  8 MB  Kt[b][c][m]
__device__ float g_Vt[B_ * C_ * MP_];    //  8 MB

__device__ __forceinline__ uint32_t smem_u32(const void* p) {
    uint32_t a;
    asm("{ .reg .u64 t; cvta.to.shared.u64 t, %1; cvt.u32.u64 %0, t; }"
        : "=r"(a) : "l"(p));
    return a;
}
__device__ __forceinline__ void cp16(uint32_t dst, const float* src) {
    asm volatile("cp.async.cg.shared.global [%0], [%1], 16;"
                 :: "r"(dst), "l"(src));
}
// zero-fill variant: src-size 0 -> 16 bytes of zeros, src not dereferenced
__device__ __forceinline__ void cp16z(uint32_t dst, const float* src, bool valid) {
    const int sz = valid ? 16 : 0;
    asm volatile("cp.async.cg.shared.global [%0], [%1], 16, %2;"
                 :: "r"(dst), "l"(src), "r"(sz));
}

// ===========================================================================
// tf32 WMMA GEMM: C[m][n] = A[m][k] @ B + bias[m]
//   block 128x128, 4 warps (2m x 2n), warp tile 64x64 = 4x4 wmma 16x16x8 frags
//   (bigger warp tile amortizes frag-load + tf32-convert: 8 loads / 16 mmas)
//   k-tile 32, double-buffered cp.async staging.
//   BCOL=false: B source row-major [k][n] (x: k=channel, n=spatial)
//   BCOL=true : B source col-major rows [n][k] (text_emb rows; n>=M_ zero-filled)
// ===========================================================================
#define A_LD   36
#define BQ_LD  132
#define BC_LD  36
#define A_FLOATS   (128 * A_LD)          // 4608
#define B_FLOATS   (128 * BC_LD)         // 4608 (>= 32*BQ_LD = 4224)
#define BUF_FLOATS (A_FLOATS + B_FLOATS) // 9216
#define GEMM_SMEM  (2 * BUF_FLOATS * 4)  // 73728 bytes

template<bool BCOL>
__device__ __forceinline__ void gemm_body(
    const float* __restrict__ A, const float* __restrict__ Bsrc,
    float* __restrict__ Cout, const float* __restrict__ bias,
    int K, int lda, int ldb, int ldc)
{
    extern __shared__ float smem[];
    const uint32_t smem_addr = smem_u32(smem);
    const int tid = threadIdx.x;          // 128 threads
    const int wid = tid >> 5, lane = tid & 31;
    const int wm = wid >> 1, wn = wid & 1;        // 2 x 2 warp grid
    const int rowBase = blockIdx.y << 7;
    const int colBase = blockIdx.x << 7;

    wmma::fragment<wmma::accumulator, 16, 16, 8, float> c[4][4];
#pragma unroll
    for (int i = 0; i < 4; i++)
#pragma unroll
        for (int j = 0; j < 4; j++) wmma::fill_fragment(c[i][j], 0.0f);

    auto stage = [&](int kt, int buf) {
        const uint32_t sA = smem_addr + buf * (BUF_FLOATS * 4);
        const uint32_t sB = sA + A_FLOATS * 4;
        const float* baseA = A + (size_t)rowBase * lda + kt * 32;
#pragma unroll
        for (int r4 = 0; r4 < 8; r4++) {            // A tile: [128][32]
            const int i4 = tid + (r4 << 7);
            const int row = i4 >> 3, c4 = (i4 & 7) << 2;
            cp16(sA + (uint32_t)(row * A_LD + c4) * 4, baseA + (size_t)row * lda + c4);
        }
        if (!BCOL) {                                 // B tile: [k=32][n=128]
            const float* baseB = Bsrc + (size_t)(kt * 32) * ldb + colBase;
#pragma unroll
            for (int r4 = 0; r4 < 8; r4++) {
                const int i4 = tid + (r4 << 7);
                const int k = i4 >> 5, n4 = (i4 & 31) << 2;
                cp16(sB + (uint32_t)(k * BQ_LD + n4) * 4, baseB + (size_t)k * ldb + n4);
            }
        } else {                                     // B tile: [n=128][k=32], pad n>=M_
            const float* baseB = Bsrc + kt * 32;
#pragma unroll
            for (int r4 = 0; r4 < 8; r4++) {
                const int i4 = tid + (r4 << 7);
                const int n = i4 >> 3, k4 = (i4 & 7) << 2;
                cp16z(sB + (uint32_t)(n * BC_LD + k4) * 4, baseB + (size_t)n * ldb + k4,
                      n < M_);
            }
        }
    };

    const int nkt = K >> 5;
    stage(0, 0);
    asm volatile("cp.async.commit_group;" ::: "memory");

    for (int kt = 0; kt < nkt; kt++) {
        const int buf = kt & 1;
        if (kt + 1 < nkt) {
            stage(kt + 1, buf ^ 1);
            asm volatile("cp.async.commit_group;" ::: "memory");
            asm volatile("cp.async.wait_group 1;" ::: "memory");
        } else {
            asm volatile("cp.async.wait_group 0;" ::: "memory");
        }
        __syncthreads();

        const float* As = smem + buf * BUF_FLOATS;
        const float* Bs = As + A_FLOATS;
#pragma unroll
        for (int ks = 0; ks < 4; ks++) {
            wmma::fragment<wmma::matrix_a, 16, 16, 8, wmma::precision::tf32,
                           wmma::row_major> a[4];
#pragma unroll
            for (int i = 0; i < 4; i++) {
                wmma::load_matrix_sync(a[i], As + (wm * 64 + i * 16) * A_LD + ks * 8, A_LD);
#pragma unroll
                for (int t = 0; t < a[i].num_elements; t++)
                    a[i].x[t] = wmma::__float_to_tf32(a[i].x[t]);
            }
#pragma unroll
            for (int j = 0; j < 4; j++) {
                if (!BCOL) {
                    wmma::fragment<wmma::matrix_b, 16, 16, 8, wmma::precision::tf32,
                                   wmma::row_major> b;
                    wmma::load_matrix_sync(b, Bs + ks * 8 * BQ_LD + (wn * 64 + j * 16),
                                           BQ_LD);
#pragma unroll
                    for (int t = 0; t < b.num_elements; t++)
                        b.x[t] = wmma::__float_to_tf32(b.x[t]);
#pragma unroll
                    for (int i = 0; i < 4; i++) wmma::mma_sync(c[i][j], a[i], b, c[i][j]);
                } else {
                    wmma::fragment<wmma::matrix_b, 16, 16, 8, wmma::precision::tf32,
                                   wmma::col_major> b;
                    wmma::load_matrix_sync(b, Bs + (wn * 64 + j * 16) * BC_LD + ks * 8,
                                           BC_LD);
#pragma unroll
                    for (int t = 0; t < b.num_elements; t++)
                        b.x[t] = wmma::__float_to_tf32(b.x[t]);
#pragma unroll
                    for (int i = 0; i < 4; i++) wmma::mma_sync(c[i][j], a[i], b, c[i][j]);
                }
            }
        }
        __syncthreads();   // staging buffers free for next prefetch / epilogue
    }

    // Epilogue: per-warp 16x16 smem patch, add bias, write row-major C
    float* patch = smem + wid * 256;
#pragma unroll
    for (int i = 0; i < 4; i++) {
        const int row0 = rowBase + wm * 64 + i * 16;
#pragma unroll
        for (int j = 0; j < 4; j++) {
            const int col0 = colBase + wn * 64 + j * 16;
            wmma::store_matrix_sync(patch, c[i][j], 16, wmma::mem_row_major);
            __syncwarp();
#pragma unroll
            for (int e = lane; e < 256; e += 32) {
                const int r = e >> 4, cc = e & 15;
                Cout[(size_t)(row0 + r) * ldc + col0 + cc] = patch[e] + bias[row0 + r];
            }
            __syncwarp();
        }
    }
}

// Qt[b] = Wq(512x512) @ x[b](512x1024) + bq   grid (8, 4, 32)
__global__ __launch_bounds__(128)
void gemm_q_kernel(const float* __restrict__ Wq, const float* __restrict__ x,
                   const float* __restrict__ bq) {
    const int b = blockIdx.z;
    gemm_body<false>(Wq, x + (size_t)b * C_ * N_, g_Qt + (size_t)b * C_ * N_,
                     bq, C_, C_, N_, N_);
}

// Kt/Vt[b] = W(512x768) @ text[b]^T + bias   grid (1, 4, 64), z = 2b+isV
__global__ __launch_bounds__(128)
void gemm_kv_kernel(const float* __restrict__ Wk, const float* __restrict__ Wv,
                    const float* __restrict__ text,
                    const float* __restrict__ bk, const float* __restrict__ bv) {
    const int z = blockIdx.z;
    const int b = z >> 1;
    const bool isV = (z & 1) != 0;
    gemm_body<true>(isV ? Wv : Wk, text + (size_t)b * M_ * TD_,
                    (isV ? g_Vt : g_Kt) + (size_t)b * C_ * MP_,
                    isV ? bv : bk, TD_, TD_, TD_, MP_);
}

// ===========================================================================
// WMMA attention: block = (128-query tile, head, batch), 256 thr (8 warps).
//   Phase 1: S[128][80] = Q·K^T — Qt is already matrix_a col_major (ld N_),
//            Kt is matrix_b row_major (ld MP_). Warp w: rows [16w,16w+16).
//   Softmax (SIMT, one thread per row; scale+mask; p normalized in smem).
//   Phase 2: O = P·V — P row_major from smem, Vt matrix_b col_major (ld MP_).
//            Accumulators stored col_major DIRECTLY into out ([B][C][H][W]).
//   Padded keys m in [77,80) forced to p=0, killing Kt/Vt bias pollution.
// ===========================================================================
#define S_LD 84   // 84 mod 32 = 20 -> 4-way LDS conflicts (ld 80 would be 16-way)

__global__ __launch_bounds__(256)
void attn_kernel(const int* __restrict__ mask, float* __restrict__ out) {
    __shared__ float Ssm[128 * S_LD];   // 43008 B
    __shared__ float msk[80];

    const int tid = threadIdx.x;
    const int wid = tid >> 5;
    const int b = blockIdx.z, h = blockIdx.y;
    const int n0 = blockIdx.x << 7;

    const float* Qbase = g_Qt + ((size_t)(b * C_ + h * HD_)) * N_ + n0; // (n,d)=ptr[d*N_+n]
    const float* Kbase = g_Kt + ((size_t)(b * C_ + h * HD_)) * MP_;     // (d,m)=ptr[d*MP_+m]
    const float* Vbase = g_Vt + ((size_t)(b * C_ + h * HD_)) * MP_;     // (m,d)=ptr[d*MP_+m]

    if (tid < 80)
        msk[tid] = (tid < M_ && mask[b * M_ + tid] != 0) ? 0.0f : -1e30f;

    // -------- Phase 1: S = Q @ K^T (warp w -> 16-row band, 5 col frags) ------
    {
        wmma::fragment<wmma::accumulator, 16, 16, 8, float> sacc[5];
#pragma unroll
        for (int j = 0; j < 5; j++) wmma::fill_fragment(sacc[j], 0.0f);
#pragma unroll
        for (int kf = 0; kf < 8; kf++) {      // d = kf*8
            wmma::fragment<wmma::matrix_a, 16, 16, 8, wmma::precision::tf32,
                           wmma::col_major> a;
            wmma::load_matrix_sync(a, Qbase + (size_t)(kf * 8) * N_ + wid * 16, N_);
#pragma unroll
            for (int t = 0; t < a.num_elements; t++)
                a.x[t] = wmma::__float_to_tf32(a.x[t]);
#pragma unroll
            for (int j = 0; j < 5; j++) {
                wmma::fragment<wmma::matrix_b, 16, 16, 8, wmma::precision::tf32,
                               wmma::row_major> kb;
                wmma::load_matrix_sync(kb, Kbase + (size_t)(kf * 8) * MP_ + j * 16, MP_);
#pragma unroll
                for (int t = 0; t < kb.num_elements; t++)
                    kb.x[t] = wmma::__float_to_tf32(kb.x[t]);
                wmma::mma_sync(sacc[j], a, kb, sacc[j]);
            }
        }
#pragma unroll
        for (int j = 0; j < 5; j++)
            wmma::store_matrix_sync(Ssm + (wid * 16) * S_LD + j * 16, sacc[j],
                                    S_LD, wmma::mem_row_major);
    }
    __syncthreads();

    // -------- Softmax: one thread per query row ------------------------------
    if (tid < 128) {
        float* row = Ssm + tid * S_LD;
        float mx = -1e30f;
#pragma unroll 7
        for (int m = 0; m < M_; m++) {
            const float s = row[m] * SCALE_ + msk[m];
            row[m] = s;
            mx = fmaxf(mx, s);
        }
        float sum = 0.0f;
#pragma unroll 7
        for (int m = 0; m < M_; m++) {
            const float p = __expf(row[m] - mx);
            row[m] = p;
            sum += p;
        }
        const float inv = 1.0f / sum;
#pragma unroll 7
        for (int m = 0; m < M_; m++) row[m] *= inv;
        row[77] = 0.0f; row[78] = 0.0f; row[79] = 0.0f;   // kill padded keys
    }
    __syncthreads();

    // -------- Phase 2: O = P @ V (warp w -> 16-row band, 4 d-frags) ----------
    {
        wmma::fragment<wmma::accumulator, 16, 16, 8, float> oacc[4];
#pragma unroll
        for (int j = 0; j < 4; j++) wmma::fill_fragment(oacc[j], 0.0f);
#pragma unroll
        for (int kf = 0; kf < 10; kf++) {     // m = kf*8
            wmma::fragment<wmma::matrix_a, 16, 16, 8, wmma::precision::tf32,
                           wmma::row_major> a;
            wmma::load_matrix_sync(a, Ssm + (wid * 16) * S_LD + kf * 8, S_LD);
#pragma unroll
            for (int t = 0; t < a.num_elements; t++)
                a.x[t] = wmma::__float_to_tf32(a.x[t]);
#pragma unroll
            for (int j = 0; j < 4; j++) {
                wmma::fragment<wmma::matrix_b, 16, 16, 8, wmma::precision::tf32,
                               wmma::col_major> vb;
                wmma::load_matrix_sync(vb, Vbase + (size_t)(j * 16) * MP_ + kf * 8, MP_);
#pragma unroll
                for (int t = 0; t < vb.num_elements; t++)
                    vb.x[t] = wmma::__float_to_tf32(vb.x[t]);
                wmma::mma_sync(oacc[j], a, vb, oacc[j]);
            }
        }
        float* obase = out + ((size_t)(b * C_ + h * HD_)) * N_ + n0 + wid * 16;
#pragma unroll
        for (int j = 0; j < 4; j++)
            wmma::store_matrix_sync(obase + (size_t)(j * 16) * N_, oacc[j],
                                    N_, wmma::mem_col_major);
    }
}

// ---------------------------------------------------------------------------
// kernel_launch — inputs: 0:x 1:text_emb 2:attention_mask 3:Wq 4:bq 5:Wk 6:bk 7:Wv 8:bv
// ---------------------------------------------------------------------------
extern "C" void kernel_launch(void* const* d_in, const int* in_sizes, int n_in,
                              void* d_out, int out_size) {
    (void)in_sizes; (void)n_in; (void)out_size;
    const float* x    = (const float*)d_in[0];
    const float* text = (const float*)d_in[1];
    const int*   mask = (const int*)d_in[2];
    const float* Wq   = (const float*)d_in[3];
    const float* bq   = (const float*)d_in[4];
    const float* Wk   = (const float*)d_in[5];
    const float* bk   = (const float*)d_in[6];
    const float* Wv   = (const float*)d_in[7];
    const float* bv   = (const float*)d_in[8];
    float* out = (float*)d_out;

    cudaFuncSetAttribute(gemm_q_kernel,  cudaFuncAttributeMaxDynamicSharedMemorySize,
                         GEMM_SMEM);
    cudaFuncSetAttribute(gemm_kv_kernel, cudaFuncAttributeMaxDynamicSharedMemorySize,
                         GEMM_SMEM);

    gemm_kv_kernel<<<dim3(1, 4, 64), 128, GEMM_SMEM>>>(Wk, Wv, text, bk, bv);
    gemm_q_kernel<<<dim3(8, 4, 32), 128, GEMM_SMEM>>>(Wq, x, bq);
    attn_kernel<<<dim3(8, 8, 32), 256>>>(mask, out);
}